// round 4
// baseline (speedup 1.0000x reference)
#include <cuda_runtime.h>
#include <cstddef>

// HelixMemory: output (8, 2558, 2048) f32.
//  rows 510..2557  : copy of memory rows 512..2557 then inputs rows 0..1
//  rows 0..509     : hierarchical pair-averages of memory rows 1024..1535
//
// Per (batch b, column d), src[r] = memory[b][1024+r][d], r in [0,512):
//   L_0[i] = (src[2i]+src[2i+1])/2 ; L_k[i] = (L_{k-1}[2i]+L_{k-1}[2i+1])/2
// Output mapping:
//   L_0[i], i>=128              -> row 126+i                (rows 254..381)
//   L_k[i], k=1..8              -> row 3*2^(8-k)-2 + i
//   L_k[i], k=1..7, i>=2^(7-k)  -> row 2^(8-k)-2 + i-2^(7-k)
//
// Single kernel, two roles:
//  - 256 pool blocks: block = (batch, 64-col group); thread = (subtree s, col dl).
//    Each thread walks its 128-row subtree computing levels 0..6 AND writes each
//    loaded row through to its copy destination (memory row 1024+r -> out row
//    1022+r), so the copy role never re-reads rows 1024..1535. L_6 values are
//    combined across the 4 subtrees via shared memory for L_7/L_8.
//  - 24576 copy blocks: one float4 per thread, covering memory rows 512..1023
//    and 1536..2557 plus inputs rows 0..1.

#define DCOLS 2048
#define MROWS 2558
#define POOL_BLOCKS 256
#define NTHREADS 256
#define COPY_F4 (8u * 1536u * 512u) /* 6,291,456 float4 */

__global__ void __launch_bounds__(NTHREADS) helix_fused(
    const float4* __restrict__ mem4,
    const float4* __restrict__ inp4,
    const float*  __restrict__ mem,
    float*        __restrict__ out,
    float4*       __restrict__ out4)
{
    int bx = blockIdx.x;
    if (bx < POOL_BLOCKS) {
        // ---- pooling role (+ copy-through of rows 1024..1535) ----
        __shared__ float l6sm[4][64];
        int b  = bx >> 5;                       // 8 batches
        int dg = bx & 31;                       // 32 column groups of 64
        int s  = threadIdx.x >> 6;              // subtree 0..3 (rows [128s,128s+128))
        int dl = threadIdx.x & 63;
        int d  = dg * 64 + dl;

        const float* src  = mem + ((size_t)b * MROWS + 1024 + 128 * s) * DCOLS + d;
        float*       outb = out + (size_t)b * MROWS * DCOLS + d;
        // copy destination for this thread's first row: out row 1022 + 128*s
        float*       cpy  = outb + (size_t)(1022 + 128 * s) * DCOLS;

        float acc[7];
        #pragma unroll
        for (int l = 0; l < 7; ++l) acc[l] = 0.0f;
        float l6val = 0.0f;

        for (int base = 0; base < 128; base += 8) {
            float v[8];
            #pragma unroll
            for (int j = 0; j < 8; ++j)
                v[j] = __ldg(src + (size_t)(base + j) * DCOLS);

            #pragma unroll
            for (int j = 0; j < 8; ++j)
                cpy[(size_t)(base + j) * DCOLS] = v[j];   // write-through copy

            #pragma unroll
            for (int j = 0; j < 8; ++j) {
                int   r = s * 128 + base + j;   // global row in [0,512)
                float x = v[j];
                #pragma unroll
                for (int l = 0; l < 7; ++l) {
                    acc[l] += x;
                    if (((r + 1) & ((2 << l) - 1)) != 0) break;  // window incomplete
                    x = acc[l] * 0.5f;
                    acc[l] = 0.0f;
                    int i = r >> (l + 1);
                    if (l == 0) {
                        if (i >= 128)
                            outb[(size_t)(126 + i) * DCOLS] = x;
                    } else {
                        int half = 256 >> l;            // 2^(8-l)
                        outb[(size_t)(3 * half - 2 + i) * DCOLS] = x;
                        if (i >= (half >> 1))
                            outb[(size_t)(half - 2 + i - (half >> 1)) * DCOLS] = x;
                    }
                    if (l == 6) l6val = x;              // L_6[s] for this column
                }
            }
        }

        l6sm[s][dl] = l6val;
        __syncthreads();

        if (threadIdx.x < 64) {                 // s == 0 threads finish the column
            float a0 = l6sm[0][dl];
            float a1 = l6sm[1][dl];
            float a2 = l6sm[2][dl];
            float a3 = l6sm[3][dl];
            float l70 = 0.5f * (a0 + a1);       // L_7[0]
            float l71 = 0.5f * (a2 + a3);       // L_7[1]
            outb[(size_t)4 * DCOLS] = l70;      // part_7 second half
            outb[(size_t)5 * DCOLS] = l71;
            outb[0]                 = l71;      // part_8 first half
            outb[(size_t)1 * DCOLS] = 0.5f * (l70 + l71);   // L_8
        }
    } else {
        // ---- copy role: one float4 per thread; skips memory rows 1024..1535 ----
        unsigned t = (unsigned)(bx - POOL_BLOCKS) * NTHREADS + threadIdx.x;
        if (t >= COPY_F4) return;
        unsigned b    = t / (1536u * 512u);
        unsigned rem  = t - b * (1536u * 512u);
        unsigned ridx = rem >> 9;                // 0..1535
        unsigned c4   = rem & 511u;
        // ridx 0..511 -> srow 512..1023 ; ridx 512..1535 -> srow 1536..2559
        unsigned srow = (ridx < 512u) ? (512u + ridx) : (1024u + ridx);
        float4 v;
        if (srow < (unsigned)MROWS)
            v = mem4[(size_t)b * (MROWS * 512) + (size_t)srow * 512 + c4];
        else
            v = inp4[(size_t)b * (1024 * 512) + (size_t)(srow - MROWS) * 512 + c4];
        out4[(size_t)b * (MROWS * 512) + (size_t)(srow - 2) * 512 + c4] = v;
    }
}

extern "C" void kernel_launch(void* const* d_in, const int* in_sizes, int n_in,
                              void* d_out, int out_size)
{
    // Identify tensors by element count (inputs: 8*1024*2048; memory: 8*2558*2048).
    const float* inputs = (const float*)d_in[0];
    const float* memory = (const float*)d_in[1];
    if (n_in >= 2 && in_sizes[0] > in_sizes[1]) {
        memory = (const float*)d_in[0];
        inputs = (const float*)d_in[1];
    }
    float* out = (float*)d_out;

    unsigned copy_blocks = (COPY_F4 + NTHREADS - 1) / NTHREADS;  // 24576
    helix_fused<<<POOL_BLOCKS + copy_blocks, NTHREADS>>>(
        (const float4*)memory, (const float4*)inputs, memory, out, (float4*)out);
}

// round 5
// speedup vs baseline: 1.0480x; 1.0480x over previous
#include <cuda_runtime.h>
#include <cstddef>

// HelixMemory: output (8, 2558, 2048) f32.
//  rows 510..2557  : copy of memory rows 512..2557 then inputs rows 0..1
//  rows 0..509     : hierarchical pair-averages of memory rows 1024..1535
//
// Per (batch b, column d), src[r] = memory[b][1024+r][d], r in [0,512):
//   L_0[i] = (src[2i]+src[2i+1])/2 ; L_k[i] = (L_{k-1}[2i]+L_{k-1}[2i+1])/2
// Output mapping:
//   L_0[i], i>=128              -> row 126+i                (rows 254..381)
//   L_k[i], k=1..8              -> row 3*2^(8-k)-2 + i
//   L_k[i], k=1..7, i>=2^(7-k)  -> row 2^(8-k)-2 + i-2^(7-k)
//
// R5: identical structure to R4, with streaming cache hints (__ldcs/__stcs)
// on every access — all traffic is read-once/write-once, so evict-first policy
// keeps the 126MB L2 from thrashing on the 168MB write-once output.

#define DCOLS 2048
#define MROWS 2558
#define POOL_BLOCKS 256
#define NTHREADS 256
#define COPY_F4 (8u * 1536u * 512u) /* 6,291,456 float4 */

__global__ void __launch_bounds__(NTHREADS) helix_fused(
    const float4* __restrict__ mem4,
    const float4* __restrict__ inp4,
    const float*  __restrict__ mem,
    float*        __restrict__ out,
    float4*       __restrict__ out4)
{
    int bx = blockIdx.x;
    if (bx < POOL_BLOCKS) {
        // ---- pooling role (+ copy-through of rows 1024..1535) ----
        __shared__ float l6sm[4][64];
        int b  = bx >> 5;                       // 8 batches
        int dg = bx & 31;                       // 32 column groups of 64
        int s  = threadIdx.x >> 6;              // subtree 0..3 (rows [128s,128s+128))
        int dl = threadIdx.x & 63;
        int d  = dg * 64 + dl;

        const float* src  = mem + ((size_t)b * MROWS + 1024 + 128 * s) * DCOLS + d;
        float*       outb = out + (size_t)b * MROWS * DCOLS + d;
        // copy destination for this thread's first row: out row 1022 + 128*s
        float*       cpy  = outb + (size_t)(1022 + 128 * s) * DCOLS;

        float acc[7];
        #pragma unroll
        for (int l = 0; l < 7; ++l) acc[l] = 0.0f;
        float l6val = 0.0f;

        for (int base = 0; base < 128; base += 8) {
            float v[8];
            #pragma unroll
            for (int j = 0; j < 8; ++j)
                v[j] = __ldcs(src + (size_t)(base + j) * DCOLS);

            #pragma unroll
            for (int j = 0; j < 8; ++j)
                __stcs(cpy + (size_t)(base + j) * DCOLS, v[j]);  // write-through copy

            #pragma unroll
            for (int j = 0; j < 8; ++j) {
                int   r = s * 128 + base + j;   // global row in [0,512)
                float x = v[j];
                #pragma unroll
                for (int l = 0; l < 7; ++l) {
                    acc[l] += x;
                    if (((r + 1) & ((2 << l) - 1)) != 0) break;  // window incomplete
                    x = acc[l] * 0.5f;
                    acc[l] = 0.0f;
                    int i = r >> (l + 1);
                    if (l == 0) {
                        if (i >= 128)
                            __stcs(outb + (size_t)(126 + i) * DCOLS, x);
                    } else {
                        int half = 256 >> l;            // 2^(8-l)
                        __stcs(outb + (size_t)(3 * half - 2 + i) * DCOLS, x);
                        if (i >= (half >> 1))
                            __stcs(outb + (size_t)(half - 2 + i - (half >> 1)) * DCOLS, x);
                    }
                    if (l == 6) l6val = x;              // L_6[s] for this column
                }
            }
        }

        l6sm[s][dl] = l6val;
        __syncthreads();

        if (threadIdx.x < 64) {                 // s == 0 threads finish the column
            float a0 = l6sm[0][dl];
            float a1 = l6sm[1][dl];
            float a2 = l6sm[2][dl];
            float a3 = l6sm[3][dl];
            float l70 = 0.5f * (a0 + a1);       // L_7[0]
            float l71 = 0.5f * (a2 + a3);       // L_7[1]
            __stcs(outb + (size_t)4 * DCOLS, l70);  // part_7 second half
            __stcs(outb + (size_t)5 * DCOLS, l71);
            __stcs(outb, l71);                      // part_8 first half
            __stcs(outb + (size_t)1 * DCOLS, 0.5f * (l70 + l71));   // L_8
        }
    } else {
        // ---- copy role: one float4 per thread; skips memory rows 1024..1535 ----
        unsigned t = (unsigned)(bx - POOL_BLOCKS) * NTHREADS + threadIdx.x;
        if (t >= COPY_F4) return;
        unsigned b    = t / (1536u * 512u);
        unsigned rem  = t - b * (1536u * 512u);
        unsigned ridx = rem >> 9;                // 0..1535
        unsigned c4   = rem & 511u;
        // ridx 0..511 -> srow 512..1023 ; ridx 512..1535 -> srow 1536..2559
        unsigned srow = (ridx < 512u) ? (512u + ridx) : (1024u + ridx);
        float4 v;
        if (srow < (unsigned)MROWS)
            v = __ldcs(mem4 + (size_t)b * (MROWS * 512) + (size_t)srow * 512 + c4);
        else
            v = __ldcs(inp4 + (size_t)b * (1024 * 512) + (size_t)(srow - MROWS) * 512 + c4);
        __stcs(out4 + (size_t)b * (MROWS * 512) + (size_t)(srow - 2) * 512 + c4, v);
    }
}

extern "C" void kernel_launch(void* const* d_in, const int* in_sizes, int n_in,
                              void* d_out, int out_size)
{
    // Identify tensors by element count (inputs: 8*1024*2048; memory: 8*2558*2048).
    const float* inputs = (const float*)d_in[0];
    const float* memory = (const float*)d_in[1];
    if (n_in >= 2 && in_sizes[0] > in_sizes[1]) {
        memory = (const float*)d_in[0];
        inputs = (const float*)d_in[1];
    }
    float* out = (float*)d_out;

    unsigned copy_blocks = (COPY_F4 + NTHREADS - 1) / NTHREADS;  // 24576
    helix_fused<<<POOL_BLOCKS + copy_blocks, NTHREADS>>>(
        (const float4*)memory, (const float4*)inputs, memory, out, (float4*)out);
}